// round 15
// baseline (speedup 1.0000x reference)
#include <cuda_runtime.h>
#include <cuda_bf16.h>
#include <cstdint>

#define Bb 256
#define Tt 256
#define Cc 384
#define Hh 64
#define NB 192

// q pre-scale: 1/sqrt(64) * log2(e)
#define SCL 0.18033688011112042f

// Scratch (device globals). q/k: [b][t][h]; vT: [b][h][t]
__device__ __align__(16) __nv_bfloat16 g_qh[Bb*Tt*Hh];
__device__ __align__(16) __nv_bfloat16 g_ql[Bb*Tt*Hh];
__device__ __align__(16) __nv_bfloat16 g_kh[Bb*Tt*Hh];
__device__ __align__(16) __nv_bfloat16 g_kl[Bb*Tt*Hh];
__device__ __align__(16) __nv_bfloat16 g_vth[Bb*Tt*Hh];
__device__ __align__(16) __nv_bfloat16 g_vtl[Bb*Tt*Hh];
__device__ __align__(16) __nv_bfloat16 g_bh[NB*Cc];     // W^T hi, K-major
__device__ __align__(16) __nv_bfloat16 g_bl[NB*Cc];

// ---------------- helpers ----------------
static __device__ __forceinline__ void hmma(float* c, const uint32_t* a, const uint32_t* b) {
    asm volatile(
        "mma.sync.aligned.m16n8k16.row.col.f32.bf16.bf16.f32 "
        "{%0,%1,%2,%3}, {%4,%5,%6,%7}, {%8,%9}, {%0,%1,%2,%3};"
        : "+f"(c[0]), "+f"(c[1]), "+f"(c[2]), "+f"(c[3])
        : "r"(a[0]), "r"(a[1]), "r"(a[2]), "r"(a[3]), "r"(b[0]), "r"(b[1]));
}
static __device__ __forceinline__ uint32_t lds32(const __nv_bfloat16* p) {
    return *(const uint32_t*)p;
}
static __device__ __forceinline__ float ex2(float x) {
    float r;
    asm("ex2.approx.ftz.f32 %0, %1;" : "=f"(r) : "f"(x));
    return r;
}
static __device__ __forceinline__ uint32_t b2u(__nv_bfloat162 v) {
    return *(uint32_t*)&v;
}
static __device__ __forceinline__ uint32_t smem_u32(const void* p) {
    uint32_t a;
    asm("{ .reg .u64 t; cvta.to.shared.u64 t, %1; cvt.u32.u64 %0, t; }" : "=r"(a) : "l"(p));
    return a;
}
static __device__ __forceinline__ void cp16(uint32_t dst, const void* src) {
    asm volatile("cp.async.cg.shared.global [%0], [%1], 16;" :: "r"(dst), "l"(src) : "memory");
}
static __device__ __forceinline__ void ldmx4(uint32_t* r, uint32_t addr) {
    asm volatile("ldmatrix.sync.aligned.m8n8.x4.shared.b16 {%0,%1,%2,%3}, [%4];"
                 : "=r"(r[0]), "=r"(r[1]), "=r"(r[2]), "=r"(r[3]) : "r"(addr));
}

// ============================================================================
// Kernel 0: split W only into K-major bf16 hi/lo (x split fused into qkv)
// ============================================================================
__global__ __launch_bounds__(256) void prep_w(const float* __restrict__ Wq,
                                              const float* __restrict__ Wk,
                                              const float* __restrict__ Wv) {
    int j = blockIdx.x * 256 + threadIdx.x;
    if (j >= Cc * NB) return;
    int k = j / NB, n = j - k * NB;
    const float* w = (n < 64) ? Wq : ((n < 128) ? Wk : Wv);
    float v = w[k * 64 + (n & 63)];
    __nv_bfloat16 hi = __float2bfloat16(v);
    float lo = v - __bfloat162float(hi);
    g_bh[n * Cc + k] = hi;
    g_bl[n * Cc + k] = __float2bfloat16(lo);
}

// ============================================================================
// Kernel 1: QKV projection — fused x-split (R12 exact, at HMMA-rate wall)
// ============================================================================
#define ASTR 72
#define STGE (640 * ASTR)          // bf16 elems/stage: (128+128+192+192)*72
__global__ __launch_bounds__(256) void qkv_hmma(const float* __restrict__ x) {
    extern __shared__ __nv_bfloat16 sm[];
    const uint32_t sb = smem_u32(sm);

    const int tid  = threadIdx.x;
    const int wid  = tid >> 5, lane = tid & 31;
    const int g    = lane >> 2, t = lane & 3;
    const int wm   = wid & 3;
    const int wn   = wid >> 2;
    const int row0 = blockIdx.x * 128;

    const int aRow = (lane & 7) + (((lane >> 3) & 1) << 3);
    const int aCol = (lane >> 4) << 3;
    const int bRow = (lane & 7) + ((lane >> 4) << 3);
    const int bCol = ((lane >> 3) & 1) << 3;

    const int xr_r  = tid >> 1;
    const int xr_c0 = (tid & 1) * 32;
    const float* xrow = x + (size_t)(row0 + xr_r) * Cc + xr_c0;

    float acc[2][12][4];
#pragma unroll
    for (int mi = 0; mi < 2; mi++)
#pragma unroll
        for (int ni = 0; ni < 12; ni++)
#pragma unroll
            for (int e = 0; e < 4; e++) acc[mi][ni][e] = 0.f;

    auto issueB = [&](int c, int st) {
        const int k0 = c * 64;
        const uint32_t sB = sb + (uint32_t)st * STGE * 2;
#pragma unroll
        for (int i = tid; i < 1536; i += 256) {          // B: 192 rows x 8 segs
            int n = i >> 3, seg = i & 7;
            uint32_t d = sB + (uint32_t)(256 * ASTR + n * ASTR + seg * 8) * 2;
            cp16(d,                  g_bh + (size_t)n * Cc + k0 + seg * 8);
            cp16(d + 192 * ASTR * 2, g_bl + (size_t)n * Cc + k0 + seg * 8);
        }
        asm volatile("cp.async.commit_group;" ::: "memory");
    };

    issueB(0, 0);
    float4 xr[8];
#pragma unroll
    for (int j = 0; j < 8; j++) xr[j] = *(const float4*)(xrow + 4 * j);

    for (int c = 0; c < 6; c++) {
        const int st = c & 1;
        const uint32_t base = sb + (uint32_t)st * STGE * 2;

        {
            __nv_bfloat16* Ah = sm + (size_t)st * STGE;
            __nv_bfloat16* Al = Ah + 128 * ASTR;
            int ro = xr_r * ASTR + xr_c0;
#pragma unroll
            for (int j = 0; j < 8; j++) {
                float4 v = xr[j];
                __nv_bfloat162 h0 = __floats2bfloat162_rn(v.x, v.y);
                __nv_bfloat162 h1 = __floats2bfloat162_rn(v.z, v.w);
                float2 f0 = __bfloat1622float2(h0), f1 = __bfloat1622float2(h1);
                __nv_bfloat162 l0 = __floats2bfloat162_rn(v.x - f0.x, v.y - f0.y);
                __nv_bfloat162 l1 = __floats2bfloat162_rn(v.z - f1.x, v.w - f1.y);
                uint2 hp, lp;
                hp.x = b2u(h0); hp.y = b2u(h1);
                lp.x = b2u(l0); lp.y = b2u(l1);
                *(uint2*)&Ah[ro + j * 4] = hp;
                *(uint2*)&Al[ro + j * 4] = lp;
            }
        }

        if (c < 5) {
#pragma unroll
            for (int j = 0; j < 8; j++) xr[j] = *(const float4*)(xrow + (c + 1) * 64 + 4 * j);
            issueB(c + 1, st ^ 1);
            asm volatile("cp.async.wait_group 1;" ::: "memory");
        } else {
            asm volatile("cp.async.wait_group 0;" ::: "memory");
        }
        __syncthreads();

        const uint32_t AhB = base;
        const uint32_t AlB = base + 128 * ASTR * 2;
        const uint32_t BhB = base + 256 * ASTR * 2;
        const uint32_t BlB = base + 448 * ASTR * 2;

#pragma unroll
        for (int s = 0; s < 4; s++) {
            const int ka = s * 16;
            uint32_t ah[2][4], al[2][4];
#pragma unroll
            for (int mi = 0; mi < 2; mi++) {
                uint32_t ao = (uint32_t)((wm * 32 + mi * 16 + aRow) * ASTR + ka + aCol) * 2;
                ldmx4(ah[mi], AhB + ao);
                ldmx4(al[mi], AlB + ao);
            }
#pragma unroll
            for (int nj = 0; nj < 6; nj++) {
                uint32_t bfh[4], bfl[4];
                uint32_t bo = (uint32_t)((wn * 96 + nj * 16 + bRow) * ASTR + ka + bCol) * 2;
                ldmx4(bfh, BhB + bo);
                ldmx4(bfl, BlB + bo);
#pragma unroll
                for (int mi = 0; mi < 2; mi++) {
                    hmma(acc[mi][2 * nj],     ah[mi], bfh);
                    hmma(acc[mi][2 * nj + 1], ah[mi], bfh + 2);
                    hmma(acc[mi][2 * nj],     al[mi], bfh);
                    hmma(acc[mi][2 * nj + 1], al[mi], bfh + 2);
                    hmma(acc[mi][2 * nj],     ah[mi], bfl);
                    hmma(acc[mi][2 * nj + 1], ah[mi], bfl + 2);
                }
            }
        }
        __syncthreads();
    }

    // ---- epilogue: split to bf16 hi/lo and scatter (q scaled, v transposed) ----
#pragma unroll
    for (int mi = 0; mi < 2; mi++) {
        int r = row0 + wm * 32 + mi * 16 + g;
        int bI = r >> 8, tt = r & 255;
#pragma unroll
        for (int ni = 0; ni < 12; ni++) {
            int col = wn * 96 + ni * 8 + 2 * t;
            float v00 = acc[mi][ni][0], v01 = acc[mi][ni][1];
            float v10 = acc[mi][ni][2], v11 = acc[mi][ni][3];
            if (col < 64) { v00 *= SCL; v01 *= SCL; v10 *= SCL; v11 *= SCL; }
            __nv_bfloat162 h0 = __floats2bfloat162_rn(v00, v01);
            float2 hf0 = __bfloat1622float2(h0);
            __nv_bfloat162 l0 = __floats2bfloat162_rn(v00 - hf0.x, v01 - hf0.y);
            __nv_bfloat162 h1 = __floats2bfloat162_rn(v10, v11);
            float2 hf1 = __bfloat1622float2(h1);
            __nv_bfloat162 l1 = __floats2bfloat162_rn(v10 - hf1.x, v11 - hf1.y);
            if (col < 128) {
                __nv_bfloat16* dh = (col < 64) ? g_qh : g_kh;
                __nv_bfloat16* dl = (col < 64) ? g_ql : g_kl;
                int cc = col & 63;
                *(__nv_bfloat162*)&dh[(size_t)r * 64 + cc]       = h0;
                *(__nv_bfloat162*)&dl[(size_t)r * 64 + cc]       = l0;
                *(__nv_bfloat162*)&dh[(size_t)(r + 8) * 64 + cc] = h1;
                *(__nv_bfloat162*)&dl[(size_t)(r + 8) * 64 + cc] = l1;
            } else {
                int cc = col - 128;
                size_t base = (size_t)bI * 16384 + (size_t)cc * 256;
                g_vth[base + tt]           = h0.x;
                g_vth[base + 256 + tt]     = h0.y;
                g_vtl[base + tt]           = l0.x;
                g_vtl[base + 256 + tt]     = l0.y;
                g_vth[base + tt + 8]       = h1.x;
                g_vth[base + 256 + tt + 8] = h1.y;
                g_vtl[base + tt + 8]       = l1.x;
                g_vtl[base + 256 + tt + 8] = l1.y;
            }
        }
    }
}

// ============================================================================
// Kernel 2: flash attention — Q-tile 128, 256 threads / 8 warps, 2 CTA/SM.
// Per-warp code identical to R14 (register-light ldmatrix feeds); K/V chunk
// loads amortized over 2x the queries.
// Smem elems: Qh[128*72] Ql[128*72] Kh/Kl/Vh/Vl[64*72 each] + floats.
// ============================================================================
#define QSTR 72
__global__ __launch_bounds__(256, 2) void attn_flash(const float* __restrict__ relk,
                                                     const float* __restrict__ relv,
                                                     float* __restrict__ out) {
    extern __shared__ char smraw[];
    const uint32_t sbA = smem_u32(smraw);
    __nv_bfloat16* Qh = (__nv_bfloat16*)smraw;          // 128*72
    __nv_bfloat16* Ql = Qh + 128 * QSTR;                // 128*72
    __nv_bfloat16* Kh = Ql + 128 * QSTR;                // 64*72
    __nv_bfloat16* Kl = Kh + 64 * QSTR;
    __nv_bfloat16* Vh = Kl + 64 * QSTR;
    __nv_bfloat16* Vl = Vh + 64 * QSTR;
    float* delta = (float*)(Vl + 64 * QSTR);   // [128][3]
    float* pde   = delta + 384;                // [128][3]
    float* pdm   = pde + 384;                  // [128][3]
    float* srelv = pdm + 384;                  // [4][64]

    const int tid  = threadIdx.x;
    const int w    = tid >> 5, lane = tid & 31;
    const int g    = lane >> 2, tq = lane & 3;
    const int b    = blockIdx.x >> 1;
    const int tile = 1 - (blockIdx.x & 1);     // heavy tile first
    const int t0   = tile * 128;
    const int nch  = (tile + 1) * 2;           // 64-key chunks

    const int bRow = (lane & 7) + ((lane >> 4) << 3);
    const int bCol = ((lane >> 3) & 1) << 3;

    const uint32_t KhB = sbA + 2u * 256 * QSTR;   // byte addr of Kh
    const uint32_t KlB = KhB + 2u * 64 * QSTR;
    const uint32_t VhB = KlB + 2u * 64 * QSTR;
    const uint32_t VlB = VhB + 2u * 64 * QSTR;

    const __nv_bfloat16* gqh = g_qh + (size_t)b * 16384 + (size_t)t0 * 64;
    const __nv_bfloat16* gql = g_ql + (size_t)b * 16384 + (size_t)t0 * 64;

    // ---- load Q tile (128 rows), preload relv, init pdiag ----
    for (int i = tid; i < 1024; i += 256) {
        int r = i >> 3, seg = i & 7;
        *(uint4*)&Qh[r * QSTR + seg * 8] = *(const uint4*)&gqh[r * 64 + seg * 8];
        *(uint4*)&Ql[r * QSTR + seg * 8] = *(const uint4*)&gql[r * 64 + seg * 8];
    }
    for (int i = tid; i < 256; i += 256) srelv[i] = relv[i];
    for (int i = tid; i < 384; i += 256) { pde[i] = 0.f; pdm[i] = 0.f; }
    __syncthreads();

    // ---- delta[r][j] = q_scaled . (relk[j+1] - relk[0]) ----
    for (int idx = tid; idx < 384; idx += 256) {
        int r = idx / 3, j = idx - r * 3;
        const float* rkd = relk + (j + 1) * 64;
        float s = 0.f;
#pragma unroll 8
        for (int h = 0; h < 64; h++) {
            float qv = __bfloat162float(Qh[r * QSTR + h]) + __bfloat162float(Ql[r * QSTR + h]);
            s += qv * (rkd[h] - relk[h]);
        }
        delta[idx] = s;
    }

    // ---- Q A-frags in registers (warp w owns rows w*16 .. w*16+15) ----
    uint32_t qfh[4][4], qfl[4][4];
    const int rl_lo = w * 16 + g, rl_hi = rl_lo + 8;
    const int tlo = t0 + rl_lo, thi = t0 + rl_hi;
#pragma unroll
    for (int ks = 0; ks < 4; ks++) {
        int ka = ks * 16 + 2 * tq;
        qfh[ks][0] = lds32(Qh + rl_lo * QSTR + ka);
        qfh[ks][1] = lds32(Qh + rl_hi * QSTR + ka);
        qfh[ks][2] = lds32(Qh + rl_lo * QSTR + ka + 8);
        qfh[ks][3] = lds32(Qh + rl_hi * QSTR + ka + 8);
        qfl[ks][0] = lds32(Ql + rl_lo * QSTR + ka);
        qfl[ks][1] = lds32(Ql + rl_hi * QSTR + ka);
        qfl[ks][2] = lds32(Ql + rl_lo * QSTR + ka + 8);
        qfl[ks][3] = lds32(Ql + rl_hi * QSTR + ka + 8);
    }

    float m0 = -1e30f, m1 = -1e30f, l0 = 0.f, l1 = 0.f;
    float O[8][4];
#pragma unroll
    for (int ht = 0; ht < 8; ht++)
#pragma unroll
        for (int e = 0; e < 4; e++) O[ht][e] = 0.f;

    for (int c = 0; c < nch; c++) {
        __syncthreads();
        const __nv_bfloat16* kh = g_kh + (size_t)b * 16384 + (size_t)c * 4096;
        const __nv_bfloat16* kl = g_kl + (size_t)b * 16384 + (size_t)c * 4096;
        const __nv_bfloat16* vh = g_vth + (size_t)b * 16384 + c * 64;
        const __nv_bfloat16* vl = g_vtl + (size_t)b * 16384 + c * 64;
        for (int i = tid; i < 512; i += 256) {
            int r = i >> 3, seg = i & 7;
            *(uint4*)&Kh[r * QSTR + seg * 8] = *(const uint4*)&kh[r * 64 + seg * 8];
            *(uint4*)&Kl[r * QSTR + seg * 8] = *(const uint4*)&kl[r * 64 + seg * 8];
            *(uint4*)&Vh[r * QSTR + seg * 8] = *(const uint4*)&vh[r * 256 + seg * 8];
            *(uint4*)&Vl[r * QSTR + seg * 8] = *(const uint4*)&vl[r * 256 + seg * 8];
        }
        __syncthreads();

        // ---- QK^T: register-light ldmatrix feeds, 3 split passes ----
        float C[8][4];
#pragma unroll
        for (int nt = 0; nt < 8; nt++)
            C[nt][0] = C[nt][1] = C[nt][2] = C[nt][3] = 0.f;
#pragma unroll
        for (int ks = 0; ks < 4; ks++) {
#pragma unroll
            for (int kb = 0; kb < 4; kb++) {
                uint32_t kfh[4], kfl[4];
                uint32_t ko = (uint32_t)((kb * 16 + bRow) * QSTR + ks * 16 + bCol) * 2;
                ldmx4(kfh, KhB + ko);
                ldmx4(kfl, KlB + ko);
#pragma unroll
                for (int e = 0; e < 2; e++) {
                    int nt = 2 * kb + e;
                    hmma(C[nt], qfh[ks], kfh + 2 * e);
                    hmma(C[nt], qfl[ks], kfh + 2 * e);
                    hmma(C[nt], qfh[ks], kfl + 2 * e);
                }
            }
        }

        // ---- mask + delta-bias + chunk max ----
        float mx0 = -1e30f, mx1 = -1e30f;
#pragma unroll
        for (int nt = 0; nt < 8; nt++) {
            int sk = c * 64 + nt * 8 + 2 * tq;
            int r0 = sk - tlo, r2 = sk - thi;
            if (r0 > 0)            C[nt][0] = -1e30f;
            else if (r0 >= -2)     C[nt][0] += delta[rl_lo * 3 + r0 + 2];
            if (r0 + 1 > 0)        C[nt][1] = -1e30f;
            else if (r0 + 1 >= -2) C[nt][1] += delta[rl_lo * 3 + r0 + 3];
            if (r2 > 0)            C[nt][2] = -1e30f;
            else if (r2 >= -2)     C[nt][2] += delta[rl_hi * 3 + r2 + 2];
            if (r2 + 1 > 0)        C[nt][3] = -1e30f;
            else if (r2 + 1 >= -2) C[nt][3] += delta[rl_hi * 3 + r2 + 3];
            mx0 = fmaxf(mx0, fmaxf(C[nt][0], C[nt][1]));
            mx1 = fmaxf(mx1, fmaxf(C[nt][2], C[nt][3]));
        }
        mx0 = fmaxf(mx0, __shfl_xor_sync(~0u, mx0, 1));
        mx0 = fmaxf(mx0, __shfl_xor_sync(~0u, mx0, 2));
        mx1 = fmaxf(mx1, __shfl_xor_sync(~0u, mx1, 1));
        mx1 = fmaxf(mx1, __shfl_xor_sync(~0u, mx1, 2));
        float nm0 = fmaxf(m0, mx0), nm1 = fmaxf(m1, mx1);
        float rs0 = ex2(m0 - nm0), rs1 = ex2(m1 - nm1);
        m0 = nm0; m1 = nm1;
        l0 *= rs0; l1 *= rs1;
#pragma unroll
        for (int ht = 0; ht < 8; ht++) {
            O[ht][0] *= rs0; O[ht][1] *= rs0; O[ht][2] *= rs1; O[ht][3] *= rs1;
        }

        // ---- exp2, sums, pdiag capture, pack P frags ----
        uint32_t ph[8][2], pl[8][2];
        float sa0 = 0.f, sa1 = 0.f;
#pragma unroll
        for (int nt = 0; nt < 8; nt++) {
            float e0 = ex2(C[nt][0] - m0), e1 = ex2(C[nt][1] - m0);
            float e2 = ex2(C[nt][2] - m1), e3 = ex2(C[nt][3] - m1);
            sa0 += e0 + e1; sa1 += e2 + e3;
            int sk = c * 64 + nt * 8 + 2 * tq;
            int r0 = sk - tlo, r2 = sk - thi;
            if ((unsigned)(r0 + 2) <= 2u) { pde[rl_lo * 3 + r0 + 2] = e0; pdm[rl_lo * 3 + r0 + 2] = m0; }
            if ((unsigned)(r0 + 3) <= 2u) { pde[rl_lo * 3 + r0 + 3] = e1; pdm[rl_lo * 3 + r0 + 3] = m0; }
            if ((unsigned)(r2 + 2) <= 2u) { pde[rl_hi * 3 + r2 + 2] = e2; pdm[rl_hi * 3 + r2 + 2] = m1; }
            if ((unsigned)(r2 + 3) <= 2u) { pde[rl_hi * 3 + r2 + 3] = e3; pdm[rl_hi * 3 + r2 + 3] = m1; }
            __nv_bfloat162 h01 = __floats2bfloat162_rn(e0, e1);
            float2 hf01 = __bfloat1622float2(h01);
            __nv_bfloat162 l01 = __floats2bfloat162_rn(e0 - hf01.x, e1 - hf01.y);
            __nv_bfloat162 h23 = __floats2bfloat162_rn(e2, e3);
            float2 hf23 = __bfloat1622float2(h23);
            __nv_bfloat162 l23 = __floats2bfloat162_rn(e2 - hf23.x, e3 - hf23.y);
            ph[nt][0] = b2u(h01); ph[nt][1] = b2u(h23);
            pl[nt][0] = b2u(l01); pl[nt][1] = b2u(l23);
        }
        sa0 += __shfl_xor_sync(~0u, sa0, 1); sa0 += __shfl_xor_sync(~0u, sa0, 2);
        sa1 += __shfl_xor_sync(~0u, sa1, 1); sa1 += __shfl_xor_sync(~0u, sa1, 2);
        l0 += sa0; l1 += sa1;

        // ---- PV: register-light ldmatrix feeds, 3 split passes ----
#pragma unroll
        for (int ks = 0; ks < 4; ks++) {
            uint32_t pah[4] = {ph[2 * ks][0], ph[2 * ks][1], ph[2 * ks + 1][0], ph[2 * ks + 1][1]};
            uint32_t pal[4] = {pl[2 * ks][0], pl[2 * ks][1], pl[2 * ks + 1][0], pl[2 * ks + 1][1]};
#pragma unroll
            for (int hb = 0; hb < 4; hb++) {
                uint32_t vfh[4], vfl[4];
                uint32_t vo = (uint32_t)((hb * 16 + bRow) * QSTR + ks * 16 + bCol) * 2;
                ldmx4(vfh, VhB + vo);
                ldmx4(vfl, VlB + vo);
#pragma unroll
                for (int e = 0; e < 2; e++) {
                    int ht = 2 * hb + e;
                    hmma(O[ht], pah, vfh + 2 * e);
                    hmma(O[ht], pal, vfh + 2 * e);
                    hmma(O[ht], pah, vfl + 2 * e);
                }
            }
        }
    }
    __syncwarp();

    // ---- epilogue: normalize + collapsed rel_v correction ----
    float inv0 = 1.f / l0, inv1 = 1.f / l1;
    float pA0 = pde[rl_lo * 3 + 0] * ex2(pdm[rl_lo * 3 + 0] - m0) * inv0;
    float pA1 = pde[rl_lo * 3 + 1] * ex2(pdm[rl_lo * 3 + 1] - m0) * inv0;
    float pA2 = pde[rl_lo * 3 + 2] * ex2(pdm[rl_lo * 3 + 2] - m0) * inv0;
    float aw0A = 1.f - pA0 - pA1 - pA2;
    float pB0 = pde[rl_hi * 3 + 0] * ex2(pdm[rl_hi * 3 + 0] - m1) * inv1;
    float pB1 = pde[rl_hi * 3 + 1] * ex2(pdm[rl_hi * 3 + 1] - m1) * inv1;
    float pB2 = pde[rl_hi * 3 + 2] * ex2(pdm[rl_hi * 3 + 2] - m1) * inv1;
    float aw0B = 1.f - pB0 - pB1 - pB2;

#pragma unroll
    for (int ht = 0; ht < 8; ht++) {
        int h = ht * 8 + 2 * tq;
        float w2a0 = aw0A * srelv[h]     + pA0 * srelv[64 + h]
                   + pA1 * srelv[128 + h] + pA2 * srelv[192 + h];
        float w2a1 = aw0A * srelv[h + 1] + pA0 * srelv[64 + h + 1]
                   + pA1 * srelv[128 + h + 1] + pA2 * srelv[192 + h + 1];
        float w2b0 = aw0B * srelv[h]     + pB0 * srelv[64 + h]
                   + pB1 * srelv[128 + h] + pB2 * srelv[192 + h];
        float w2b1 = aw0B * srelv[h + 1] + pB0 * srelv[64 + h + 1]
                   + pB1 * srelv[128 + h + 1] + pB2 * srelv[192 + h + 1];
        *(float2*)&out[((size_t)b * 256 + tlo) * 64 + h] =
            make_float2(O[ht][0] * inv0 + w2a0, O[ht][1] * inv0 + w2a1);
        *(float2*)&out[((size_t)b * 256 + thi) * 64 + h] =
            make_float2(O[ht][2] * inv1 + w2b0, O[ht][3] * inv1 + w2b1);
    }
}

// ============================================================================
extern "C" void kernel_launch(void* const* d_in, const int* in_sizes, int n_in,
                              void* d_out, int out_size) {
    const float* x    = (const float*)d_in[0];
    const float* Wq   = (const float*)d_in[1];
    const float* Wk   = (const float*)d_in[2];
    const float* Wv   = (const float*)d_in[3];
    const float* relk = (const float*)d_in[4];
    const float* relv = (const float*)d_in[5];
    float* out = (float*)d_out;

    prep_w<<<(Cc * NB + 255) / 256, 256>>>(Wq, Wk, Wv);

    int gemm_smem = 2 * STGE * (int)sizeof(__nv_bfloat16);   // 184320 B
    cudaFuncSetAttribute(qkv_hmma, cudaFuncAttributeMaxDynamicSharedMemorySize, gemm_smem);
    qkv_hmma<<<(Bb * Tt) / 128, 256, gemm_smem>>>(x);

    int attn_smem = (256 * QSTR + 4 * 64 * QSTR) * (int)sizeof(__nv_bfloat16)
                  + (384 * 3 + 256) * (int)sizeof(float);     // 79360 B
    cudaFuncSetAttribute(attn_flash, cudaFuncAttributeMaxDynamicSharedMemorySize, attn_smem);
    attn_flash<<<Bb * 2, 256, attn_smem>>>(relk, relv, out);
}

// round 17
// speedup vs baseline: 1.5494x; 1.5494x over previous
#include <cuda_runtime.h>
#include <cuda_bf16.h>
#include <cstdint>

#define Bb 256
#define Tt 256
#define Cc 384
#define Hh 64
#define NB 192

// q pre-scale: 1/sqrt(64) * log2(e)
#define SCL 0.18033688011112042f

// Scratch (device globals). q/k: [b][t][h]; vT: [b][h][t]
__device__ __align__(16) __nv_bfloat16 g_qh[Bb*Tt*Hh];
__device__ __align__(16) __nv_bfloat16 g_ql[Bb*Tt*Hh];
__device__ __align__(16) __nv_bfloat16 g_kh[Bb*Tt*Hh];
__device__ __align__(16) __nv_bfloat16 g_kl[Bb*Tt*Hh];
__device__ __align__(16) __nv_bfloat16 g_vth[Bb*Tt*Hh];
__device__ __align__(16) __nv_bfloat16 g_vtl[Bb*Tt*Hh];
__device__ __align__(16) __nv_bfloat16 g_bh[NB*Cc];     // W^T hi, K-major
__device__ __align__(16) __nv_bfloat16 g_bl[NB*Cc];

// ---------------- helpers ----------------
static __device__ __forceinline__ void hmma(float* c, const uint32_t* a, const uint32_t* b) {
    asm volatile(
        "mma.sync.aligned.m16n8k16.row.col.f32.bf16.bf16.f32 "
        "{%0,%1,%2,%3}, {%4,%5,%6,%7}, {%8,%9}, {%0,%1,%2,%3};"
        : "+f"(c[0]), "+f"(c[1]), "+f"(c[2]), "+f"(c[3])
        : "r"(a[0]), "r"(a[1]), "r"(a[2]), "r"(a[3]), "r"(b[0]), "r"(b[1]));
}
static __device__ __forceinline__ uint32_t lds32(const __nv_bfloat16* p) {
    return *(const uint32_t*)p;
}
static __device__ __forceinline__ float ex2(float x) {
    float r;
    asm("ex2.approx.ftz.f32 %0, %1;" : "=f"(r) : "f"(x));
    return r;
}
static __device__ __forceinline__ uint32_t b2u(__nv_bfloat162 v) {
    return *(uint32_t*)&v;
}
static __device__ __forceinline__ uint32_t smem_u32(const void* p) {
    uint32_t a;
    asm("{ .reg .u64 t; cvta.to.shared.u64 t, %1; cvt.u32.u64 %0, t; }" : "=r"(a) : "l"(p));
    return a;
}
static __device__ __forceinline__ void cp16(uint32_t dst, const void* src) {
    asm volatile("cp.async.cg.shared.global [%0], [%1], 16;" :: "r"(dst), "l"(src) : "memory");
}
static __device__ __forceinline__ void ldmx4(uint32_t* r, uint32_t addr) {
    asm volatile("ldmatrix.sync.aligned.m8n8.x4.shared.b16 {%0,%1,%2,%3}, [%4];"
                 : "=r"(r[0]), "=r"(r[1]), "=r"(r[2]), "=r"(r[3]) : "r"(addr));
}

// ============================================================================
// Kernel 0: split W only into K-major bf16 hi/lo (x split fused into qkv)
// ============================================================================
__global__ __launch_bounds__(256) void prep_w(const float* __restrict__ Wq,
                                              const float* __restrict__ Wk,
                                              const float* __restrict__ Wv) {
    int j = blockIdx.x * 256 + threadIdx.x;
    if (j >= Cc * NB) return;
    int k = j / NB, n = j - k * NB;
    const float* w = (n < 64) ? Wq : ((n < 128) ? Wk : Wv);
    float v = w[k * 64 + (n & 63)];
    __nv_bfloat16 hi = __float2bfloat16(v);
    float lo = v - __bfloat162float(hi);
    g_bh[n * Cc + k] = hi;
    g_bl[n * Cc + k] = __float2bfloat16(lo);
}

// ============================================================================
// Kernel 1: QKV projection — fused x-split (R12 exact, at HMMA-rate wall)
// ============================================================================
#define ASTR 72
#define STGE (640 * ASTR)          // bf16 elems/stage: (128+128+192+192)*72
__global__ __launch_bounds__(256) void qkv_hmma(const float* __restrict__ x) {
    extern __shared__ __nv_bfloat16 sm[];
    const uint32_t sb = smem_u32(sm);

    const int tid  = threadIdx.x;
    const int wid  = tid >> 5, lane = tid & 31;
    const int g    = lane >> 2, t = lane & 3;
    const int wm   = wid & 3;
    const int wn   = wid >> 2;
    const int row0 = blockIdx.x * 128;

    const int aRow = (lane & 7) + (((lane >> 3) & 1) << 3);
    const int aCol = (lane >> 4) << 3;
    const int bRow = (lane & 7) + ((lane >> 4) << 3);
    const int bCol = ((lane >> 3) & 1) << 3;

    const int xr_r  = tid >> 1;
    const int xr_c0 = (tid & 1) * 32;
    const float* xrow = x + (size_t)(row0 + xr_r) * Cc + xr_c0;

    float acc[2][12][4];
#pragma unroll
    for (int mi = 0; mi < 2; mi++)
#pragma unroll
        for (int ni = 0; ni < 12; ni++)
#pragma unroll
            for (int e = 0; e < 4; e++) acc[mi][ni][e] = 0.f;

    auto issueB = [&](int c, int st) {
        const int k0 = c * 64;
        const uint32_t sB = sb + (uint32_t)st * STGE * 2;
#pragma unroll
        for (int i = tid; i < 1536; i += 256) {          // B: 192 rows x 8 segs
            int n = i >> 3, seg = i & 7;
            uint32_t d = sB + (uint32_t)(256 * ASTR + n * ASTR + seg * 8) * 2;
            cp16(d,                  g_bh + (size_t)n * Cc + k0 + seg * 8);
            cp16(d + 192 * ASTR * 2, g_bl + (size_t)n * Cc + k0 + seg * 8);
        }
        asm volatile("cp.async.commit_group;" ::: "memory");
    };

    issueB(0, 0);
    float4 xr[8];
#pragma unroll
    for (int j = 0; j < 8; j++) xr[j] = *(const float4*)(xrow + 4 * j);

    for (int c = 0; c < 6; c++) {
        const int st = c & 1;
        const uint32_t base = sb + (uint32_t)st * STGE * 2;

        {
            __nv_bfloat16* Ah = sm + (size_t)st * STGE;
            __nv_bfloat16* Al = Ah + 128 * ASTR;
            int ro = xr_r * ASTR + xr_c0;
#pragma unroll
            for (int j = 0; j < 8; j++) {
                float4 v = xr[j];
                __nv_bfloat162 h0 = __floats2bfloat162_rn(v.x, v.y);
                __nv_bfloat162 h1 = __floats2bfloat162_rn(v.z, v.w);
                float2 f0 = __bfloat1622float2(h0), f1 = __bfloat1622float2(h1);
                __nv_bfloat162 l0 = __floats2bfloat162_rn(v.x - f0.x, v.y - f0.y);
                __nv_bfloat162 l1 = __floats2bfloat162_rn(v.z - f1.x, v.w - f1.y);
                uint2 hp, lp;
                hp.x = b2u(h0); hp.y = b2u(h1);
                lp.x = b2u(l0); lp.y = b2u(l1);
                *(uint2*)&Ah[ro + j * 4] = hp;
                *(uint2*)&Al[ro + j * 4] = lp;
            }
        }

        if (c < 5) {
#pragma unroll
            for (int j = 0; j < 8; j++) xr[j] = *(const float4*)(xrow + (c + 1) * 64 + 4 * j);
            issueB(c + 1, st ^ 1);
            asm volatile("cp.async.wait_group 1;" ::: "memory");
        } else {
            asm volatile("cp.async.wait_group 0;" ::: "memory");
        }
        __syncthreads();

        const uint32_t AhB = base;
        const uint32_t AlB = base + 128 * ASTR * 2;
        const uint32_t BhB = base + 256 * ASTR * 2;
        const uint32_t BlB = base + 448 * ASTR * 2;

#pragma unroll
        for (int s = 0; s < 4; s++) {
            const int ka = s * 16;
            uint32_t ah[2][4], al[2][4];
#pragma unroll
            for (int mi = 0; mi < 2; mi++) {
                uint32_t ao = (uint32_t)((wm * 32 + mi * 16 + aRow) * ASTR + ka + aCol) * 2;
                ldmx4(ah[mi], AhB + ao);
                ldmx4(al[mi], AlB + ao);
            }
#pragma unroll
            for (int nj = 0; nj < 6; nj++) {
                uint32_t bfh[4], bfl[4];
                uint32_t bo = (uint32_t)((wn * 96 + nj * 16 + bRow) * ASTR + ka + bCol) * 2;
                ldmx4(bfh, BhB + bo);
                ldmx4(bfl, BlB + bo);
#pragma unroll
                for (int mi = 0; mi < 2; mi++) {
                    hmma(acc[mi][2 * nj],     ah[mi], bfh);
                    hmma(acc[mi][2 * nj + 1], ah[mi], bfh + 2);
                    hmma(acc[mi][2 * nj],     al[mi], bfh);
                    hmma(acc[mi][2 * nj + 1], al[mi], bfh + 2);
                    hmma(acc[mi][2 * nj],     ah[mi], bfl);
                    hmma(acc[mi][2 * nj + 1], ah[mi], bfl + 2);
                }
            }
        }
        __syncthreads();
    }

    // ---- epilogue: split to bf16 hi/lo and scatter (q scaled, v transposed) ----
#pragma unroll
    for (int mi = 0; mi < 2; mi++) {
        int r = row0 + wm * 32 + mi * 16 + g;
        int bI = r >> 8, tt = r & 255;
#pragma unroll
        for (int ni = 0; ni < 12; ni++) {
            int col = wn * 96 + ni * 8 + 2 * t;
            float v00 = acc[mi][ni][0], v01 = acc[mi][ni][1];
            float v10 = acc[mi][ni][2], v11 = acc[mi][ni][3];
            if (col < 64) { v00 *= SCL; v01 *= SCL; v10 *= SCL; v11 *= SCL; }
            __nv_bfloat162 h0 = __floats2bfloat162_rn(v00, v01);
            float2 hf0 = __bfloat1622float2(h0);
            __nv_bfloat162 l0 = __floats2bfloat162_rn(v00 - hf0.x, v01 - hf0.y);
            __nv_bfloat162 h1 = __floats2bfloat162_rn(v10, v11);
            float2 hf1 = __bfloat1622float2(h1);
            __nv_bfloat162 l1 = __floats2bfloat162_rn(v10 - hf1.x, v11 - hf1.y);
            if (col < 128) {
                __nv_bfloat16* dh = (col < 64) ? g_qh : g_kh;
                __nv_bfloat16* dl = (col < 64) ? g_ql : g_kl;
                int cc = col & 63;
                *(__nv_bfloat162*)&dh[(size_t)r * 64 + cc]       = h0;
                *(__nv_bfloat162*)&dl[(size_t)r * 64 + cc]       = l0;
                *(__nv_bfloat162*)&dh[(size_t)(r + 8) * 64 + cc] = h1;
                *(__nv_bfloat162*)&dl[(size_t)(r + 8) * 64 + cc] = l1;
            } else {
                int cc = col - 128;
                size_t base = (size_t)bI * 16384 + (size_t)cc * 256;
                g_vth[base + tt]           = h0.x;
                g_vth[base + 256 + tt]     = h0.y;
                g_vtl[base + tt]           = l0.x;
                g_vtl[base + 256 + tt]     = l0.y;
                g_vth[base + tt + 8]       = h1.x;
                g_vth[base + 256 + tt + 8] = h1.y;
                g_vtl[base + tt + 8]       = l1.x;
                g_vtl[base + 256 + tt + 8] = l1.y;
            }
        }
    }
}

// ============================================================================
// Kernel 2: flash attention — R14 config (64-Q tile, 128 thr, occ 3, ldmatrix)
// + split cp.async K/V groups: V load overlaps QK^T + softmax.
// Smem: 6 x 64*72 bf16 regions (Qh,Ql,Kh,Kl,Vh,Vl) then float region.
// ============================================================================
#define QSTR 72
__global__ __launch_bounds__(128, 3) void attn_flash(const float* __restrict__ relk,
                                                     const float* __restrict__ relv,
                                                     float* __restrict__ out) {
    extern __shared__ char smraw[];
    const uint32_t sbA = smem_u32(smraw);
    __nv_bfloat16* Qh = (__nv_bfloat16*)smraw;
    __nv_bfloat16* Ql = Qh + 64 * QSTR;
    float* delta = (float*)(smraw + 6 * 64 * QSTR * 2);  // [64][3] after 6 bf16 regions
    float* pde   = delta + 192;
    float* pdm   = pde + 192;
    float* srelv = pdm + 192;                            // [4][64]

    const int tid  = threadIdx.x;
    const int w    = tid >> 5, lane = tid & 31;
    const int g    = lane >> 2, tq = lane & 3;
    const int b    = blockIdx.x >> 2;
    const int tile = 3 - (blockIdx.x & 3);
    const int t0   = tile * 64;
    const int nch  = tile + 1;

    const int bRow = (lane & 7) + ((lane >> 4) << 3);
    const int bCol = ((lane >> 3) & 1) << 3;

    const uint32_t KhB = sbA + 2u * 128 * QSTR;   // byte addr of Kh
    const uint32_t KlB = KhB + 2u * 64 * QSTR;
    const uint32_t VhB = KlB + 2u * 64 * QSTR;
    const uint32_t VlB = VhB + 2u * 64 * QSTR;

    const __nv_bfloat16* gqh = g_qh + (size_t)b * 16384 + (size_t)t0 * 64;
    const __nv_bfloat16* gql = g_ql + (size_t)b * 16384 + (size_t)t0 * 64;

    for (int i = tid; i < 512; i += 128) {
        int r = i >> 3, seg = i & 7;
        *(uint4*)&Qh[r * QSTR + seg * 8] = *(const uint4*)&gqh[r * 64 + seg * 8];
        *(uint4*)&Ql[r * QSTR + seg * 8] = *(const uint4*)&gql[r * 64 + seg * 8];
    }
    for (int i = tid; i < 256; i += 128) srelv[i] = relv[i];
    for (int i = tid; i < 192; i += 128) { pde[i] = 0.f; pdm[i] = 0.f; }
    __syncthreads();

    for (int idx = tid; idx < 192; idx += 128) {
        int r = idx / 3, j = idx - r * 3;
        const float* rkd = relk + (j + 1) * 64;
        float s = 0.f;
#pragma unroll 8
        for (int h = 0; h < 64; h++) {
            float qv = __bfloat162float(Qh[r * QSTR + h]) + __bfloat162float(Ql[r * QSTR + h]);
            s += qv * (rkd[h] - relk[h]);
        }
        delta[idx] = s;
    }

    uint32_t qfh[4][4], qfl[4][4];
    const int rl_lo = w * 16 + g, rl_hi = rl_lo + 8;
    const int tlo = t0 + rl_lo, thi = t0 + rl_hi;
#pragma unroll
    for (int ks = 0; ks < 4; ks++) {
        int ka = ks * 16 + 2 * tq;
        qfh[ks][0] = lds32(Qh + rl_lo * QSTR + ka);
        qfh[ks][1] = lds32(Qh + rl_hi * QSTR + ka);
        qfh[ks][2] = lds32(Qh + rl_lo * QSTR + ka + 8);
        qfh[ks][3] = lds32(Qh + rl_hi * QSTR + ka + 8);
        qfl[ks][0] = lds32(Ql + rl_lo * QSTR + ka);
        qfl[ks][1] = lds32(Ql + rl_hi * QSTR + ka);
        qfl[ks][2] = lds32(Ql + rl_lo * QSTR + ka + 8);
        qfl[ks][3] = lds32(Ql + rl_hi * QSTR + ka + 8);
    }

    float m0 = -1e30f, m1 = -1e30f, l0 = 0.f, l1 = 0.f;
    float O[8][4];
#pragma unroll
    for (int ht = 0; ht < 8; ht++)
#pragma unroll
        for (int e = 0; e < 4; e++) O[ht][e] = 0.f;

    for (int c = 0; c < nch; c++) {
        __syncthreads();   // previous PV reads complete before overwrite
        const __nv_bfloat16* kh = g_kh + (size_t)b * 16384 + (size_t)c * 4096;
        const __nv_bfloat16* kl = g_kl + (size_t)b * 16384 + (size_t)c * 4096;
        const __nv_bfloat16* vh = g_vth + (size_t)b * 16384 + c * 64;
        const __nv_bfloat16* vl = g_vtl + (size_t)b * 16384 + c * 64;
        // ---- group 1: K tiles ----
        for (int i = tid; i < 512; i += 128) {
            int r = i >> 3, seg = i & 7;
            uint32_t o = (uint32_t)(r * QSTR + seg * 8) * 2;
            cp16(KhB + o, kh + r * 64 + seg * 8);
            cp16(KlB + o, kl + r * 64 + seg * 8);
        }
        asm volatile("cp.async.commit_group;" ::: "memory");
        // ---- group 2: V tiles (overlaps QK^T below) ----
        for (int i = tid; i < 512; i += 128) {
            int r = i >> 3, seg = i & 7;
            uint32_t o = (uint32_t)(r * QSTR + seg * 8) * 2;
            cp16(VhB + o, vh + r * 256 + seg * 8);
            cp16(VlB + o, vl + r * 256 + seg * 8);
        }
        asm volatile("cp.async.commit_group;" ::: "memory");
        asm volatile("cp.async.wait_group 1;" ::: "memory");   // K landed
        __syncthreads();

        // ---- QK^T: register-light ldmatrix feeds, 3 split passes ----
        float C[8][4];
#pragma unroll
        for (int nt = 0; nt < 8; nt++)
            C[nt][0] = C[nt][1] = C[nt][2] = C[nt][3] = 0.f;
#pragma unroll
        for (int ks = 0; ks < 4; ks++) {
#pragma unroll
            for (int kb = 0; kb < 4; kb++) {
                uint32_t kfh[4], kfl[4];
                uint32_t ko = (uint32_t)((kb * 16 + bRow) * QSTR + ks * 16 + bCol) * 2;
                ldmx4(kfh, KhB + ko);
                ldmx4(kfl, KlB + ko);
#pragma unroll
                for (int e = 0; e < 2; e++) {
                    int nt = 2 * kb + e;
                    hmma(C[nt], qfh[ks], kfh + 2 * e);
                    hmma(C[nt], qfl[ks], kfh + 2 * e);
                    hmma(C[nt], qfh[ks], kfl + 2 * e);
                }
            }
        }

        // ---- mask + delta-bias + chunk max ----
        float mx0 = -1e30f, mx1 = -1e30f;
#pragma unroll
        for (int nt = 0; nt < 8; nt++) {
            int sk = c * 64 + nt * 8 + 2 * tq;
            int r0 = sk - tlo, r2 = sk - thi;
            if (r0 > 0)            C[nt][0] = -1e30f;
            else if (r0 >= -2)     C[nt][0] += delta[rl_lo * 3 + r0 + 2];
            if (r0 + 1 > 0)        C[nt][1] = -1e30f;
            else if (r0 + 1 >= -2) C[nt][1] += delta[rl_lo * 3 + r0 + 3];
            if (r2 > 0)            C[nt][2] = -1e30f;
            else if (r2 >= -2)     C[nt][2] += delta[rl_hi * 3 + r2 + 2];
            if (r2 + 1 > 0)        C[nt][3] = -1e30f;
            else if (r2 + 1 >= -2) C[nt][3] += delta[rl_hi * 3 + r2 + 3];
            mx0 = fmaxf(mx0, fmaxf(C[nt][0], C[nt][1]));
            mx1 = fmaxf(mx1, fmaxf(C[nt][2], C[nt][3]));
        }
        mx0 = fmaxf(mx0, __shfl_xor_sync(~0u, mx0, 1));
        mx0 = fmaxf(mx0, __shfl_xor_sync(~0u, mx0, 2));
        mx1 = fmaxf(mx1, __shfl_xor_sync(~0u, mx1, 1));
        mx1 = fmaxf(mx1, __shfl_xor_sync(~0u, mx1, 2));
        float nm0 = fmaxf(m0, mx0), nm1 = fmaxf(m1, mx1);
        float rs0 = ex2(m0 - nm0), rs1 = ex2(m1 - nm1);
        m0 = nm0; m1 = nm1;
        l0 *= rs0; l1 *= rs1;
#pragma unroll
        for (int ht = 0; ht < 8; ht++) {
            O[ht][0] *= rs0; O[ht][1] *= rs0; O[ht][2] *= rs1; O[ht][3] *= rs1;
        }

        // ---- exp2, sums, pdiag capture, pack P frags ----
        uint32_t ph[8][2], pl[8][2];
        float sa0 = 0.f, sa1 = 0.f;
#pragma unroll
        for (int nt = 0; nt < 8; nt++) {
            float e0 = ex2(C[nt][0] - m0), e1 = ex2(C[nt][1] - m0);
            float e2 = ex2(C[nt][2] - m1), e3 = ex2(C[nt][3] - m1);
            sa0 += e0 + e1; sa1 += e2 + e3;
            int sk = c * 64 + nt * 8 + 2 * tq;
            int r0 = sk - tlo, r2 = sk - thi;
            if ((unsigned)(r0 + 2) <= 2u) { pde[rl_lo * 3 + r0 + 2] = e0; pdm[rl_lo * 3 + r0 + 2] = m0; }
            if ((unsigned)(r0 + 3) <= 2u) { pde[rl_lo * 3 + r0 + 3] = e1; pdm[rl_lo * 3 + r0 + 3] = m0; }
            if ((unsigned)(r2 + 2) <= 2u) { pde[rl_hi * 3 + r2 + 2] = e2; pdm[rl_hi * 3 + r2 + 2] = m1; }
            if ((unsigned)(r2 + 3) <= 2u) { pde[rl_hi * 3 + r2 + 3] = e3; pdm[rl_hi * 3 + r2 + 3] = m1; }
            __nv_bfloat162 h01 = __floats2bfloat162_rn(e0, e1);
            float2 hf01 = __bfloat1622float2(h01);
            __nv_bfloat162 l01 = __floats2bfloat162_rn(e0 - hf01.x, e1 - hf01.y);
            __nv_bfloat162 h23 = __floats2bfloat162_rn(e2, e3);
            float2 hf23 = __bfloat1622float2(h23);
            __nv_bfloat162 l23 = __floats2bfloat162_rn(e2 - hf23.x, e3 - hf23.y);
            ph[nt][0] = b2u(h01); ph[nt][1] = b2u(h23);
            pl[nt][0] = b2u(l01); pl[nt][1] = b2u(l23);
        }
        sa0 += __shfl_xor_sync(~0u, sa0, 1); sa0 += __shfl_xor_sync(~0u, sa0, 2);
        sa1 += __shfl_xor_sync(~0u, sa1, 1); sa1 += __shfl_xor_sync(~0u, sa1, 2);
        l0 += sa0; l1 += sa1;

        // ---- wait for V, then PV: register-light ldmatrix feeds ----
        asm volatile("cp.async.wait_group 0;" ::: "memory");
        __syncthreads();
#pragma unroll
        for (int ks = 0; ks < 4; ks++) {
            uint32_t pah[4] = {ph[2 * ks][0], ph[2 * ks][1], ph[2 * ks + 1][0], ph[2 * ks + 1][1]};
            uint32_t pal[4] = {pl[2 * ks][0], pl[2 * ks][1], pl[2 * ks + 1][0], pl[2 * ks + 1][1]};
#pragma unroll
            for (int hb = 0; hb < 4; hb++) {
                uint32_t vfh[4], vfl[4];
                uint32_t vo = (uint32_t)((hb * 16 + bRow) * QSTR + ks * 16 + bCol) * 2;
                ldmx4(vfh, VhB + vo);
                ldmx4(vfl, VlB + vo);
#pragma unroll
                for (int e = 0; e < 2; e++) {
                    int ht = 2 * hb + e;
                    hmma(O[ht], pah, vfh + 2 * e);
                    hmma(O[ht], pal, vfh + 2 * e);
                    hmma(O[ht], pah, vfl + 2 * e);
                }
            }
        }
    }
    __syncwarp();

    // ---- epilogue: normalize + collapsed rel_v correction ----
    float inv0 = 1.f / l0, inv1 = 1.f / l1;
    float pA0 = pde[rl_lo * 3 + 0] * ex2(pdm[rl_lo * 3 + 0] - m0) * inv0;
    float pA1 = pde[rl_lo * 3 + 1] * ex2(pdm[rl_lo * 3 + 1] - m0) * inv0;
    float pA2 = pde[rl_lo * 3 + 2] * ex2(pdm[rl_lo * 3 + 2] - m0) * inv0;
    float aw0A = 1.f - pA0 - pA1 - pA2;
    float pB0 = pde[rl_hi * 3 + 0] * ex2(pdm[rl_hi * 3 + 0] - m1) * inv1;
    float pB1 = pde[rl_hi * 3 + 1] * ex2(pdm[rl_hi * 3 + 1] - m1) * inv1;
    float pB2 = pde[rl_hi * 3 + 2] * ex2(pdm[rl_hi * 3 + 2] - m1) * inv1;
    float aw0B = 1.f - pB0 - pB1 - pB2;

#pragma unroll
    for (int ht = 0; ht < 8; ht++) {
        int h = ht * 8 + 2 * tq;
        float w2a0 = aw0A * srelv[h]     + pA0 * srelv[64 + h]
                   + pA1 * srelv[128 + h] + pA2 * srelv[192 + h];
        float w2a1 = aw0A * srelv[h + 1] + pA0 * srelv[64 + h + 1]
                   + pA1 * srelv[128 + h + 1] + pA2 * srelv[192 + h + 1];
        float w2b0 = aw0B * srelv[h]     + pB0 * srelv[64 + h]
                   + pB1 * srelv[128 + h] + pB2 * srelv[192 + h];
        float w2b1 = aw0B * srelv[h + 1] + pB0 * srelv[64 + h + 1]
                   + pB1 * srelv[128 + h + 1] + pB2 * srelv[192 + h + 1];
        *(float2*)&out[((size_t)b * 256 + tlo) * 64 + h] =
            make_float2(O[ht][0] * inv0 + w2a0, O[ht][1] * inv0 + w2a1);
        *(float2*)&out[((size_t)b * 256 + thi) * 64 + h] =
            make_float2(O[ht][2] * inv1 + w2b0, O[ht][3] * inv1 + w2b1);
    }
}

// ============================================================================
extern "C" void kernel_launch(void* const* d_in, const int* in_sizes, int n_in,
                              void* d_out, int out_size) {
    const float* x    = (const float*)d_in[0];
    const float* Wq   = (const float*)d_in[1];
    const float* Wk   = (const float*)d_in[2];
    const float* Wv   = (const float*)d_in[3];
    const float* relk = (const float*)d_in[4];
    const float* relv = (const float*)d_in[5];
    float* out = (float*)d_out;

    prep_w<<<(Cc * NB + 255) / 256, 256>>>(Wq, Wk, Wv);

    int gemm_smem = 2 * STGE * (int)sizeof(__nv_bfloat16);   // 184320 B
    cudaFuncSetAttribute(qkv_hmma, cudaFuncAttributeMaxDynamicSharedMemorySize, gemm_smem);
    qkv_hmma<<<(Bb * Tt) / 128, 256, gemm_smem>>>(x);

    int attn_smem = 6 * 64 * QSTR * (int)sizeof(__nv_bfloat16)
                  + (192 + 192 + 192 + 256) * (int)sizeof(float);
    cudaFuncSetAttribute(attn_flash, cudaFuncAttributeMaxDynamicSharedMemorySize, attn_smem);
    attn_flash<<<Bb * 4, 128, attn_smem>>>(relk, relv, out);
}